// round 8
// baseline (speedup 1.0000x reference)
#include <cuda_runtime.h>

#define BB 128
#define NT 64    // n1: templates
#define NM 128   // n2: label points

__device__ float g_gpool[BB * 32 * NM];

typedef unsigned long long ull;

__device__ __forceinline__ ull pk(float lo, float hi) {
    ull r; asm("mov.b64 %0,{%1,%2};" : "=l"(r) : "f"(lo), "f"(hi)); return r;
}
__device__ __forceinline__ ull pk1(float v) {
    ull r; asm("mov.b64 %0,{%1,%1};" : "=l"(r) : "f"(v)); return r;
}
__device__ __forceinline__ void upk(ull v, float& lo, float& hi) {
    asm("mov.b64 {%0,%1},%2;" : "=f"(lo), "=f"(hi) : "l"(v));
}
__device__ __forceinline__ ull ffma2(ull a, ull b, ull c) {
    ull d; asm("fma.rn.f32x2 %0,%1,%2,%3;" : "=l"(d) : "l"(a), "l"(b), "l"(c)); return d;
}

// ---------------------------------------------------------------------------
// Kernel 1: global-attention branch -> g_gpool (B,32,NM)
// grid 512 = B*4 m-tiles of 32; block 128 = 4 warps. Warp w owns ml in
// [8w,8w+8) as 4 (ml0,ml1) pairs; lane = output channel o. Templates (n)
// processed in TWO halves of 32 (Bn/Tn/xoT recomputed per half) to cut
// smem to ~45KB -> 4-5 blocks/SM. Weights in smem ([c][o], conflict-free),
// f32x2 packed accumulators, 2 exchange buffers, 3 syncwarps per 8 pixels.
// ---------------------------------------------------------------------------
__global__ __launch_bounds__(128, 4) void k_gpool(
    const float* __restrict__ x_label, const float* __restrict__ x_object,
    const float* __restrict__ template_xyz,
    const float* __restrict__ gw_w1, const float* __restrict__ gw_b1,
    const float* __restrict__ gw_s,  const float* __restrict__ gw_t,
    const float* __restrict__ gw_w2, const float* __restrict__ gw_b2,
    const float* __restrict__ gm_w1, const float* __restrict__ gm_s1,
    const float* __restrict__ gm_t1, const float* __restrict__ gm_w2,
    const float* __restrict__ gm_s2, const float* __restrict__ gm_t2)
{
    __shared__ float xoT[32][33];          // [nh][c], current half
    __shared__ float Bn[32][33];           // [nh][o]
    __shared__ float Tn[32][33];           // [nh][o]
    __shared__ float As[32][33];           // [ml][o]
    __shared__ float Wst[4][32][32];       // [0]=gw_w2 [1]=gm1c [2]=gm2 [3]=gw_w1, all [c][o]
    __shared__ float b2s[32], ct2s[32];
    __shared__ float umxs[4][8][32];       // per-warp partial max across halves
    __shared__ __align__(16) ull bufA[4][32][4];   // exchange (xls aliases in setup)
    __shared__ __align__(16) ull bufB[4][32][4];

    float* xls = (float*)&bufA[0][0][0];   // [c*32+ml], setup only

    const int tid = threadIdx.x;
    const int b = blockIdx.x >> 2, mt = blockIdx.x & 3;

    // ---- setup: stage weights + x_label slice ----
    for (int i = tid; i < 1024; i += 128) {
        int c = i >> 5, ml = i & 31;
        xls[c * 32 + ml] = x_label[(size_t)b * 4096 + c * 128 + mt * 32 + ml];
    }
    for (int i = tid; i < 1024; i += 128) {
        int c = i >> 5, o = i & 31;
        Wst[0][c][o] = gw_w2[o * 32 + c];
        Wst[1][c][o] = gm_s1[o] * gm_w1[o * 35 + 3 + c];
        Wst[2][c][o] = gm_s2[o] * gm_w2[o * 32 + c];
        Wst[3][c][o] = gw_w1[o * 32 + c];
    }
    if (tid < 32) { b2s[tid] = gw_b2[tid]; ct2s[tid] = gm_t2[tid]; }
    __syncthreads();

    // ---- As[ml][o] = s*(W1@xl + b1) + t   (lane=o, broadcast xls reads) ----
    for (int i = tid; i < 1024; i += 128) {
        int o = i & 31, ml = i >> 5;
        float a = 0.f;
        #pragma unroll
        for (int c = 0; c < 32; c++) a += Wst[3][c][o] * xls[c * 32 + ml];
        As[ml][o] = gw_s[o] * (a + gw_b1[o]) + gw_t[o];
    }

    const int w = tid >> 5, o = tid & 31;
    const ull bias2p = pk1(b2s[o]), biasTp = pk1(ct2s[o]);

    #pragma unroll 1
    for (int h = 0; h < 2; h++) {
        __syncthreads();   // prior-half readers done; As ready on h==0
        for (int i = tid; i < 1024; i += 128) {
            int c = i >> 5, nh = i & 31;
            xoT[nh][c] = x_object[(size_t)b * 2048 + c * 64 + 32 * h + nh];
        }
        __syncthreads();
        // Bn/Tn for this half (lane=o, broadcast xoT reads)
        for (int i = tid; i < 1024; i += 128) {
            int oo = i & 31, nh = i >> 5;
            float a = 0.f;
            #pragma unroll
            for (int c = 0; c < 32; c++) a += Wst[3][c][oo] * xoT[nh][c];
            Bn[nh][oo] = -gw_s[oo] * a;
            const float* tx = template_xyz + (size_t)b * 192 + (32 * h + nh) * 3;
            Tn[nh][oo] = gm_s1[oo] * (gm_w1[oo * 35] * tx[0] +
                                      gm_w1[oo * 35 + 1] * tx[1] +
                                      gm_w1[oo * 35 + 2] * tx[2]) + gm_t1[oo];
        }
        __syncthreads();

        #pragma unroll 1
        for (int t = 0; t < 4; t++) {
            const int ml0 = w * 8 + 2 * t, ml1 = ml0 + 1;
            const float as0 = As[ml0][o], as1 = As[ml1][o];
            float um0 = 0.f, um1 = 0.f;

            #pragma unroll 1
            for (int j = 0; j < 8; j++) {
                const int n0 = 4 * j;

                // gw1 (folded) + leaky, packed (ml0,ml1) per n
                ull L0, L1, L2, L3;
                {
                    float bn0 = Bn[n0 + 0][o], bn1 = Bn[n0 + 1][o];
                    float bn2 = Bn[n0 + 2][o], bn3 = Bn[n0 + 3][o];
                    float za, zb;
                    za = as0 + bn0; zb = as1 + bn0;
                    L0 = pk(fmaxf(za, 0.2f * za), fmaxf(zb, 0.2f * zb));
                    za = as0 + bn1; zb = as1 + bn1;
                    L1 = pk(fmaxf(za, 0.2f * za), fmaxf(zb, 0.2f * zb));
                    za = as0 + bn2; zb = as1 + bn2;
                    L2 = pk(fmaxf(za, 0.2f * za), fmaxf(zb, 0.2f * zb));
                    za = as0 + bn3; zb = as1 + bn3;
                    L3 = pk(fmaxf(za, 0.2f * za), fmaxf(zb, 0.2f * zb));
                }
                *(ulonglong2*)&bufA[w][o][0] = make_ulonglong2(L0, L1);
                *(ulonglong2*)&bufA[w][o][2] = make_ulonglong2(L2, L3);
                __syncwarp();

                // gw2: q = b2 + W2 @ L
                ull q0 = bias2p, q1 = bias2p, q2 = bias2p, q3 = bias2p;
                #pragma unroll
                for (int c = 0; c < 32; c++) {
                    ull wp = pk1(Wst[0][c][o]);
                    ulonglong2 va = *(const ulonglong2*)&bufA[w][c][0];
                    ulonglong2 vb = *(const ulonglong2*)&bufA[w][c][2];
                    q0 = ffma2(va.x, wp, q0); q1 = ffma2(va.y, wp, q1);
                    q2 = ffma2(vb.x, wp, q2); q3 = ffma2(vb.y, wp, q3);
                }

                // gate: g = sigmoid(q) * xo[n][o]
                {
                    float qa, qb, xo;
                    upk(q0, qa, qb); xo = xoT[n0 + 0][o];
                    q0 = pk(__fdividef(xo, 1.f + __expf(-qa)),
                            __fdividef(xo, 1.f + __expf(-qb)));
                    upk(q1, qa, qb); xo = xoT[n0 + 1][o];
                    q1 = pk(__fdividef(xo, 1.f + __expf(-qa)),
                            __fdividef(xo, 1.f + __expf(-qb)));
                    upk(q2, qa, qb); xo = xoT[n0 + 2][o];
                    q2 = pk(__fdividef(xo, 1.f + __expf(-qa)),
                            __fdividef(xo, 1.f + __expf(-qb)));
                    upk(q3, qa, qb); xo = xoT[n0 + 3][o];
                    q3 = pk(__fdividef(xo, 1.f + __expf(-qa)),
                            __fdividef(xo, 1.f + __expf(-qb)));
                }
                *(ulonglong2*)&bufB[w][o][0] = make_ulonglong2(q0, q1);
                *(ulonglong2*)&bufB[w][o][2] = make_ulonglong2(q2, q3);
                __syncwarp();

                // gm1: t = Tn + Wm1 @ g, relu
                ull t0 = pk1(Tn[n0 + 0][o]), t1 = pk1(Tn[n0 + 1][o]);
                ull t2 = pk1(Tn[n0 + 2][o]), t3 = pk1(Tn[n0 + 3][o]);
                #pragma unroll
                for (int c = 0; c < 32; c++) {
                    ull wp = pk1(Wst[1][c][o]);
                    ulonglong2 va = *(const ulonglong2*)&bufB[w][c][0];
                    ulonglong2 vb = *(const ulonglong2*)&bufB[w][c][2];
                    t0 = ffma2(va.x, wp, t0); t1 = ffma2(va.y, wp, t1);
                    t2 = ffma2(vb.x, wp, t2); t3 = ffma2(vb.y, wp, t3);
                }
                {
                    float ta, tb;
                    upk(t0, ta, tb); t0 = pk(fmaxf(ta, 0.f), fmaxf(tb, 0.f));
                    upk(t1, ta, tb); t1 = pk(fmaxf(ta, 0.f), fmaxf(tb, 0.f));
                    upk(t2, ta, tb); t2 = pk(fmaxf(ta, 0.f), fmaxf(tb, 0.f));
                    upk(t3, ta, tb); t3 = pk(fmaxf(ta, 0.f), fmaxf(tb, 0.f));
                }
                // all lanes finished reading bufA before writing bufB (pre-sync)
                *(ulonglong2*)&bufA[w][o][0] = make_ulonglong2(t0, t1);
                *(ulonglong2*)&bufA[w][o][2] = make_ulonglong2(t2, t3);
                __syncwarp();

                // gm2: u = t2b + Wm2 @ r ; relu+max folded
                ull u0 = biasTp, u1 = biasTp, u2 = biasTp, u3 = biasTp;
                #pragma unroll
                for (int c = 0; c < 32; c++) {
                    ull wp = pk1(Wst[2][c][o]);
                    ulonglong2 va = *(const ulonglong2*)&bufA[w][c][0];
                    ulonglong2 vb = *(const ulonglong2*)&bufA[w][c][2];
                    u0 = ffma2(va.x, wp, u0); u1 = ffma2(va.y, wp, u1);
                    u2 = ffma2(vb.x, wp, u2); u3 = ffma2(vb.y, wp, u3);
                }
                {
                    float ua, ub;
                    upk(u0, ua, ub); um0 = fmaxf(um0, ua); um1 = fmaxf(um1, ub);
                    upk(u1, ua, ub); um0 = fmaxf(um0, ua); um1 = fmaxf(um1, ub);
                    upk(u2, ua, ub); um0 = fmaxf(um0, ua); um1 = fmaxf(um1, ub);
                    upk(u3, ua, ub); um0 = fmaxf(um0, ua); um1 = fmaxf(um1, ub);
                }
            }

            if (h == 0) {
                umxs[w][2 * t][o] = um0;
                umxs[w][2 * t + 1][o] = um1;
            } else {
                size_t base = ((size_t)b * 32 + o) * NM + mt * 32;
                g_gpool[base + ml0] = fmaxf(umxs[w][2 * t][o], um0);
                g_gpool[base + ml1] = fmaxf(umxs[w][2 * t + 1][o], um1);
            }
        }
    }
}

// ---------------------------------------------------------------------------
// Kernel 2: cosine sim + argmax gather + MLP + final layers -> out
// grid 512 = B*4 m-tiles of 32; block 256: ml = tid&31, p = tid>>5 (8 parts).
// ---------------------------------------------------------------------------
__global__ __launch_bounds__(256) void k_out(
    const float* __restrict__ x_label, const float* __restrict__ x_object,
    const float* __restrict__ template_xyz,
    const float* __restrict__ mlp_w1, const float* __restrict__ mlp_s1,
    const float* __restrict__ mlp_t1, const float* __restrict__ mlp_w2,
    const float* __restrict__ mlp_s2, const float* __restrict__ mlp_t2,
    const float* __restrict__ fl_w1, const float* __restrict__ fl_s1,
    const float* __restrict__ fl_t1, const float* __restrict__ fl_w2,
    const float* __restrict__ fl_b2, float* __restrict__ out)
{
    __shared__ float xo_s[32][64];
    __shared__ float w1T[68][32];
    __shared__ float w2T[32][32];
    __shared__ float na_s[64];
    __shared__ float hs[32][33];
    __shared__ float fu[64][33];
    __shared__ float o1s[64][33];
    __shared__ float sb[8][32];
    __shared__ int   si[8][32];

    const int b = blockIdx.x >> 2, mt = blockIdx.x & 3;
    const int tid = threadIdx.x, ml = tid & 31, p = tid >> 5;
    const int m = mt * 32 + ml;

    for (int i = tid; i < 2048; i += 256)
        ((float*)xo_s)[i] = x_object[(size_t)b * 2048 + i];
    for (int i = tid; i < 68 * 32; i += 256) {
        int j = i >> 5, o = i & 31;
        w1T[j][o] = mlp_w1[o * 68 + j];
    }
    for (int i = tid; i < 1024; i += 256) {
        int c = i >> 5, o = i & 31;
        w2T[c][o] = mlp_w2[o * 32 + c];
    }
    for (int i = tid; i < 1024; i += 256) {
        int c = i >> 5, q = i & 31;
        fu[32 + c][q] = g_gpool[((size_t)b * 32 + c) * NM + mt * 32 + q];
    }
    __syncthreads();
    if (tid < 64) {
        float s = 0.f;
        #pragma unroll
        for (int c = 0; c < 32; c++) { float v = xo_s[c][tid]; s += v * v; }
        na_s[tid] = sqrtf(s);
    }

    float xl[32];
    #pragma unroll
    for (int c = 0; c < 32; c++)
        xl[c] = x_label[(size_t)b * 4096 + c * 128 + m];
    float nb = 0.f;
    #pragma unroll
    for (int c = 0; c < 32; c++) nb += xl[c] * xl[c];
    nb = sqrtf(nb);
    __syncthreads();

    float best = -3.4e38f; int bidx = 8 * p;
    #pragma unroll 1
    for (int n = 8 * p; n < 8 * p + 8; n++) {
        float num = 0.f;
        #pragma unroll
        for (int c = 0; c < 32; c++) num += xo_s[c][n] * xl[c];
        float cs = num / fmaxf(na_s[n] * nb, 1e-8f);
        if (cs > best) { best = cs; bidx = n; }
    }
    sb[p][ml] = best; si[p][ml] = bidx;
    __syncthreads();
    best = sb[0][ml]; bidx = si[0][ml];
    #pragma unroll
    for (int pp = 1; pp < 8; pp++)
        if (sb[pp][ml] > best) { best = sb[pp][ml]; bidx = si[pp][ml]; }

    float hr[4];
    {
        const float* tx = template_xyz + (size_t)b * 192 + bidx * 3;
        float a0 = tx[0], a1 = tx[1], a2 = tx[2];
        #pragma unroll
        for (int oo = 0; oo < 4; oo++) {
            int o = 4 * p + oo;
            hr[oo] = w1T[0][o] * best + w1T[1][o] * a0 +
                     w1T[2][o] * a1 + w1T[3][o] * a2;
        }
    }
    #pragma unroll
    for (int c = 0; c < 32; c++) {
        float xoc = xo_s[c][bidx];
        #pragma unroll
        for (int oo = 0; oo < 4; oo++) hr[oo] += w1T[4 + c][4 * p + oo] * xoc;
    }
    #pragma unroll
    for (int c = 0; c < 32; c++) {
        float v = xl[c];
        #pragma unroll
        for (int oo = 0; oo < 4; oo++) hr[oo] += w1T[36 + c][4 * p + oo] * v;
    }
    #pragma unroll
    for (int oo = 0; oo < 4; oo++) {
        int o = 4 * p + oo;
        hs[ml][o] = fmaxf(mlp_s1[o] * hr[oo] + mlp_t1[o], 0.f);
    }
    __syncthreads();

    float h2r[4] = {0.f, 0.f, 0.f, 0.f};
    #pragma unroll
    for (int c = 0; c < 32; c++) {
        float v = hs[ml][c];
        #pragma unroll
        for (int oo = 0; oo < 4; oo++) h2r[oo] += w2T[c][4 * p + oo] * v;
    }
    #pragma unroll
    for (int oo = 0; oo < 4; oo++) {
        int o = 4 * p + oo;
        fu[o][ml] = fmaxf(mlp_s2[o] * h2r[oo] + mlp_t2[o], 0.f);
    }
    __syncthreads();

    float fv[64];
    #pragma unroll
    for (int c = 0; c < 64; c++) fv[c] = fu[c][ml];
    #pragma unroll 2
    for (int oo = 0; oo < 8; oo++) {
        int o = 8 * p + oo;
        float acc = 0.f;
        const float4* wp4 = (const float4*)(fl_w1 + o * 64);
        #pragma unroll
        for (int c4 = 0; c4 < 16; c4++) {
            float4 ww = __ldg(&wp4[c4]);
            acc += ww.x * fv[4 * c4] + ww.y * fv[4 * c4 + 1] +
                   ww.z * fv[4 * c4 + 2] + ww.w * fv[4 * c4 + 3];
        }
        o1s[o][ml] = fmaxf(fl_s1[o] * acc + fl_t1[o], 0.f);
    }
    __syncthreads();

    float ov[64];
    #pragma unroll
    for (int c = 0; c < 64; c++) ov[c] = o1s[c][ml];
    #pragma unroll 2
    for (int oo = 0; oo < 8; oo++) {
        int o = 8 * p + oo;
        float acc = fl_b2[o];
        const float4* wp4 = (const float4*)(fl_w2 + o * 64);
        #pragma unroll
        for (int c4 = 0; c4 < 16; c4++) {
            float4 ww = __ldg(&wp4[c4]);
            acc += ww.x * ov[4 * c4] + ww.y * ov[4 * c4 + 1] +
                   ww.z * ov[4 * c4 + 2] + ww.w * ov[4 * c4 + 3];
        }
        out[((size_t)b * 64 + o) * NM + m] = acc;
    }
}

extern "C" void kernel_launch(void* const* d_in, const int* in_sizes, int n_in,
                              void* d_out, int out_size)
{
    const float* x_label      = (const float*)d_in[0];
    const float* x_object     = (const float*)d_in[1];
    const float* template_xyz = (const float*)d_in[2];
    const float* mlp_w1 = (const float*)d_in[3];
    const float* mlp_s1 = (const float*)d_in[4];
    const float* mlp_t1 = (const float*)d_in[5];
    const float* mlp_w2 = (const float*)d_in[6];
    const float* mlp_s2 = (const float*)d_in[7];
    const float* mlp_t2 = (const float*)d_in[8];
    const float* gw_w1  = (const float*)d_in[9];
    const float* gw_b1  = (const float*)d_in[10];
    const float* gw_s   = (const float*)d_in[11];
    const float* gw_t   = (const float*)d_in[12];
    const float* gw_w2  = (const float*)d_in[13];
    const float* gw_b2  = (const float*)d_in[14];
    const float* gm_w1  = (const float*)d_in[15];
    const float* gm_s1  = (const float*)d_in[16];
    const float* gm_t1  = (const float*)d_in[17];
    const float* gm_w2  = (const float*)d_in[18];
    const float* gm_s2  = (const float*)d_in[19];
    const float* gm_t2  = (const float*)d_in[20];
    const float* fl_w1  = (const float*)d_in[21];
    const float* fl_s1  = (const float*)d_in[22];
    const float* fl_t1  = (const float*)d_in[23];
    const float* fl_w2  = (const float*)d_in[24];
    const float* fl_b2  = (const float*)d_in[25];

    k_gpool<<<512, 128>>>(x_label, x_object, template_xyz,
                          gw_w1, gw_b1, gw_s, gw_t, gw_w2, gw_b2,
                          gm_w1, gm_s1, gm_t1, gm_w2, gm_s2, gm_t2);
    k_out<<<512, 256>>>(x_label, x_object, template_xyz,
                        mlp_w1, mlp_s1, mlp_t1, mlp_w2, mlp_s2, mlp_t2,
                        fl_w1, fl_s1, fl_t1, fl_w2, fl_b2, (float*)d_out);
}

// round 10
// speedup vs baseline: 1.2428x; 1.2428x over previous
#include <cuda_runtime.h>

#define BB 128
#define NT 64    // n1: templates
#define NM 128   // n2: label points

__device__ float g_gpool[BB * 32 * NM];

typedef unsigned long long ull;

__device__ __forceinline__ ull pk(float lo, float hi) {
    ull r; asm("mov.b64 %0,{%1,%2};" : "=l"(r) : "f"(lo), "f"(hi)); return r;
}
__device__ __forceinline__ ull pk1(float v) {
    ull r; asm("mov.b64 %0,{%1,%1};" : "=l"(r) : "f"(v)); return r;
}
__device__ __forceinline__ void upk(ull v, float& lo, float& hi) {
    asm("mov.b64 {%0,%1},%2;" : "=f"(lo), "=f"(hi) : "l"(v));
}
__device__ __forceinline__ ull ffma2(ull a, ull b, ull c) {
    ull d; asm("fma.rn.f32x2 %0,%1,%2,%3;" : "=l"(d) : "l"(a), "l"(b), "l"(c)); return d;
}

// ---------------------------------------------------------------------------
// Kernel 1: global-attention branch -> g_gpool (B,32,NM)
// R5 structure (best measured ~203us) + triple-buffered exchange
// (3 syncwarps per 4-pixel chunk instead of 6). bufG aliases xls (4KB,
// dead after As precompute); bufT aliases Wst (12KB, dead after register
// hoist). bufL is the dedicated 2KB buffer. Each alias target is >= 2KB.
// ---------------------------------------------------------------------------
__global__ __launch_bounds__(128) void k_gpool(
    const float* __restrict__ x_label, const float* __restrict__ x_object,
    const float* __restrict__ template_xyz,
    const float* __restrict__ gw_w1, const float* __restrict__ gw_b1,
    const float* __restrict__ gw_s,  const float* __restrict__ gw_t,
    const float* __restrict__ gw_w2, const float* __restrict__ gw_b2,
    const float* __restrict__ gm_w1, const float* __restrict__ gm_s1,
    const float* __restrict__ gm_t1, const float* __restrict__ gm_w2,
    const float* __restrict__ gm_s2, const float* __restrict__ gm_t2)
{
    __shared__ float xoT[64][33];                    // [n][c] padded
    __shared__ float Bn[64][33];                     // [n][o] = -s*(W1@xo)
    __shared__ float Tn[64][33];                     // [n][o] gm1 xyz + t1
    __shared__ float As[32][33];                     // [ml][o]
    __shared__ __align__(16) float Wst[3][32][32];   // staging; bufT alias
    __shared__ __align__(16) float xls[32][32];      // staging; bufG alias
    __shared__ __align__(16) float bufL[4][32][4];   // exchange buffer L
    __shared__ float b2s[32], ct2s[32];

    const int tid = threadIdx.x;
    const int b = blockIdx.x >> 2, mt = blockIdx.x & 3;

    // ---- stage inputs + weights (coalesced) ----
    for (int i = tid; i < 2048; i += 128) {
        int c = i >> 6, n = i & 63;
        xoT[n][c] = x_object[(size_t)b * 2048 + i];
    }
    for (int i = tid; i < 1024; i += 128) {
        int c = i >> 5, ml = i & 31;
        xls[c][ml] = x_label[(size_t)b * 4096 + c * 128 + mt * 32 + ml];
    }
    for (int i = tid; i < 1024; i += 128) {
        int c = i >> 5, o = i & 31;
        Wst[0][c][o] = gw_w2[o * 32 + c];
        Wst[1][c][o] = gm_s1[o] * gm_w1[o * 35 + 3 + c];
        Wst[2][c][o] = gm_s2[o] * gm_w2[o * 32 + c];
    }
    if (tid < 32) { b2s[tid] = gw_b2[tid]; ct2s[tid] = gm_t2[tid]; }
    __syncthreads();

    // ---- per-(b,n) and per-(b,m) precompute ----
    for (int i = tid; i < 2048; i += 128) {
        int o = i >> 6, n = i & 63;
        float a = 0.f;
        #pragma unroll
        for (int c = 0; c < 32; c++) a += gw_w1[o * 32 + c] * xoT[n][c];
        Bn[n][o] = -gw_s[o] * a;
        const float* tx = template_xyz + (size_t)b * 192 + n * 3;
        Tn[n][o] = gm_s1[o] * (gm_w1[o * 35] * tx[0] + gm_w1[o * 35 + 1] * tx[1] +
                               gm_w1[o * 35 + 2] * tx[2]) + gm_t1[o];
    }
    for (int i = tid; i < 1024; i += 128) {
        int o = i >> 5, ml = i & 31;
        float a = 0.f;
        #pragma unroll
        for (int c = 0; c < 32; c++) a += gw_w1[o * 32 + c] * xls[c][ml];
        As[ml][o] = gw_s[o] * a + gw_s[o] * gw_b1[o] + gw_t[o];
    }
    __syncthreads();

    // ---- hoist weight columns into registers (const-indexed only) ----
    const int w = tid >> 5, o = tid & 31;
    float w2r[32], wm1r[32], wm2r[32];
    #pragma unroll
    for (int c = 0; c < 32; c++) {
        w2r[c]  = Wst[0][c][o];
        wm1r[c] = Wst[1][c][o];
        wm2r[c] = Wst[2][c][o];
    }
    const float bias2 = b2s[o], biasT = ct2s[o];
    __syncthreads();   // Wst and xls become exchange buffers from here on

    // exchange buffer views (per warp: 32 lanes x 4 floats = 128 floats)
    float* bufGp = &xls[0][0];
    float* bufTp = &Wst[0][0][0];
    float4* mbL = (float4*)&bufL[w][o][0];
    float4* mbG = (float4*)(bufGp + (w * 32 + o) * 4);
    float4* mbT = (float4*)(bufTp + (w * 32 + o) * 4);
    const ulonglong2* bvL = (const ulonglong2*)&bufL[w][0][0];
    const ulonglong2* bvG = (const ulonglong2*)(bufGp + w * 128);
    const ulonglong2* bvT = (const ulonglong2*)(bufTp + w * 128);

    #pragma unroll 1
    for (int mi = 0; mi < 8; mi++) {
        const int ml = w * 8 + mi;
        const float as = As[ml][o];
        float um = 0.f;

        #pragma unroll 1
        for (int j = 0; j < 16; j++) {
            const int n0 = 4 * j;

            // stage gw1 (folded): leaky(as + Bn[n][o]) -> bufL
            float z0 = as + Bn[n0 + 0][o];
            float z1 = as + Bn[n0 + 1][o];
            float z2 = as + Bn[n0 + 2][o];
            float z3 = as + Bn[n0 + 3][o];
            *mbL = make_float4(fmaxf(z0, 0.2f * z0), fmaxf(z1, 0.2f * z1),
                               fmaxf(z2, 0.2f * z2), fmaxf(z3, 0.2f * z3));
            __syncwarp();

            // stage gw2: q = b2 + W2 @ L  (packed pixel pairs)
            ull q01 = pk1(bias2), q23 = q01;
            #pragma unroll
            for (int c = 0; c < 32; c++) {
                ull wp = pk1(w2r[c]);
                ulonglong2 v = bvL[c];
                q01 = ffma2(v.x, wp, q01);
                q23 = ffma2(v.y, wp, q23);
            }

            // gate: g = sigmoid(q) * xo[n][o] -> bufG
            float q0, q1, q2, q3;
            upk(q01, q0, q1); upk(q23, q2, q3);
            float g0 = __fdividef(xoT[n0 + 0][o], 1.f + __expf(-q0));
            float g1 = __fdividef(xoT[n0 + 1][o], 1.f + __expf(-q1));
            float g2 = __fdividef(xoT[n0 + 2][o], 1.f + __expf(-q2));
            float g3 = __fdividef(xoT[n0 + 3][o], 1.f + __expf(-q3));
            *mbG = make_float4(g0, g1, g2, g3);
            __syncwarp();

            // stage gm1: t = Tn + Wm1 @ g, relu -> bufT
            ull t01 = pk(Tn[n0 + 0][o], Tn[n0 + 1][o]);
            ull t23 = pk(Tn[n0 + 2][o], Tn[n0 + 3][o]);
            #pragma unroll
            for (int c = 0; c < 32; c++) {
                ull wp = pk1(wm1r[c]);
                ulonglong2 v = bvG[c];
                t01 = ffma2(v.x, wp, t01);
                t23 = ffma2(v.y, wp, t23);
            }
            float t0, t1, t2, t3;
            upk(t01, t0, t1); upk(t23, t2, t3);
            *mbT = make_float4(fmaxf(t0, 0.f), fmaxf(t1, 0.f),
                               fmaxf(t2, 0.f), fmaxf(t3, 0.f));
            __syncwarp();

            // stage gm2: u = t2b + Wm2 @ r ; relu+max folded into um
            ull u01 = pk1(biasT), u23 = u01;
            #pragma unroll
            for (int c = 0; c < 32; c++) {
                ull wp = pk1(wm2r[c]);
                ulonglong2 v = bvT[c];
                u01 = ffma2(v.x, wp, u01);
                u23 = ffma2(v.y, wp, u23);
            }
            float u0, u1, u2, u3;
            upk(u01, u0, u1); upk(u23, u2, u3);
            um = fmaxf(um, fmaxf(fmaxf(u0, u1), fmaxf(u2, u3)));
        }

        g_gpool[((size_t)b * 32 + o) * NM + mt * 32 + ml] = um;
    }
}

// ---------------------------------------------------------------------------
// Kernel 2: cosine sim + argmax gather + MLP + final layers -> out
// grid 512 = B*4 m-tiles of 32; block 256 (unchanged, 58.8us measured)
// ---------------------------------------------------------------------------
__global__ __launch_bounds__(256) void k_out(
    const float* __restrict__ x_label, const float* __restrict__ x_object,
    const float* __restrict__ template_xyz,
    const float* __restrict__ mlp_w1, const float* __restrict__ mlp_s1,
    const float* __restrict__ mlp_t1, const float* __restrict__ mlp_w2,
    const float* __restrict__ mlp_s2, const float* __restrict__ mlp_t2,
    const float* __restrict__ fl_w1, const float* __restrict__ fl_s1,
    const float* __restrict__ fl_t1, const float* __restrict__ fl_w2,
    const float* __restrict__ fl_b2, float* __restrict__ out)
{
    __shared__ float xo_s[32][64];
    __shared__ float w1T[68][32];
    __shared__ float w2T[32][32];
    __shared__ float na_s[64];
    __shared__ float hs[32][33];
    __shared__ float fu[64][33];
    __shared__ float o1s[64][33];
    __shared__ float sb[8][32];
    __shared__ int   si[8][32];

    const int b = blockIdx.x >> 2, mt = blockIdx.x & 3;
    const int tid = threadIdx.x, ml = tid & 31, p = tid >> 5;
    const int m = mt * 32 + ml;

    for (int i = tid; i < 2048; i += 256)
        ((float*)xo_s)[i] = x_object[(size_t)b * 2048 + i];
    for (int i = tid; i < 68 * 32; i += 256) {
        int j = i >> 5, o = i & 31;
        w1T[j][o] = mlp_w1[o * 68 + j];
    }
    for (int i = tid; i < 1024; i += 256) {
        int c = i >> 5, o = i & 31;
        w2T[c][o] = mlp_w2[o * 32 + c];
    }
    for (int i = tid; i < 1024; i += 256) {
        int c = i >> 5, q = i & 31;
        fu[32 + c][q] = g_gpool[((size_t)b * 32 + c) * NM + mt * 32 + q];
    }
    __syncthreads();
    if (tid < 64) {
        float s = 0.f;
        #pragma unroll
        for (int c = 0; c < 32; c++) { float v = xo_s[c][tid]; s += v * v; }
        na_s[tid] = sqrtf(s);
    }

    float xl[32];
    #pragma unroll
    for (int c = 0; c < 32; c++)
        xl[c] = x_label[(size_t)b * 4096 + c * 128 + m];
    float nb = 0.f;
    #pragma unroll
    for (int c = 0; c < 32; c++) nb += xl[c] * xl[c];
    nb = sqrtf(nb);
    __syncthreads();

    float best = -3.4e38f; int bidx = 8 * p;
    #pragma unroll 1
    for (int n = 8 * p; n < 8 * p + 8; n++) {
        float num = 0.f;
        #pragma unroll
        for (int c = 0; c < 32; c++) num += xo_s[c][n] * xl[c];
        float cs = num / fmaxf(na_s[n] * nb, 1e-8f);
        if (cs > best) { best = cs; bidx = n; }
    }
    sb[p][ml] = best; si[p][ml] = bidx;
    __syncthreads();
    best = sb[0][ml]; bidx = si[0][ml];
    #pragma unroll
    for (int pp = 1; pp < 8; pp++)
        if (sb[pp][ml] > best) { best = sb[pp][ml]; bidx = si[pp][ml]; }

    float hr[4];
    {
        const float* tx = template_xyz + (size_t)b * 192 + bidx * 3;
        float a0 = tx[0], a1 = tx[1], a2 = tx[2];
        #pragma unroll
        for (int oo = 0; oo < 4; oo++) {
            int o = 4 * p + oo;
            hr[oo] = w1T[0][o] * best + w1T[1][o] * a0 +
                     w1T[2][o] * a1 + w1T[3][o] * a2;
        }
    }
    #pragma unroll
    for (int c = 0; c < 32; c++) {
        float xoc = xo_s[c][bidx];
        #pragma unroll
        for (int oo = 0; oo < 4; oo++) hr[oo] += w1T[4 + c][4 * p + oo] * xoc;
    }
    #pragma unroll
    for (int c = 0; c < 32; c++) {
        float v = xl[c];
        #pragma unroll
        for (int oo = 0; oo < 4; oo++) hr[oo] += w1T[36 + c][4 * p + oo] * v;
    }
    #pragma unroll
    for (int oo = 0; oo < 4; oo++) {
        int o = 4 * p + oo;
        hs[ml][o] = fmaxf(mlp_s1[o] * hr[oo] + mlp_t1[o], 0.f);
    }
    __syncthreads();

    float h2r[4] = {0.f, 0.f, 0.f, 0.f};
    #pragma unroll
    for (int c = 0; c < 32; c++) {
        float v = hs[ml][c];
        #pragma unroll
        for (int oo = 0; oo < 4; oo++) h2r[oo] += w2T[c][4 * p + oo] * v;
    }
    #pragma unroll
    for (int oo = 0; oo < 4; oo++) {
        int o = 4 * p + oo;
        fu[o][ml] = fmaxf(mlp_s2[o] * h2r[oo] + mlp_t2[o], 0.f);
    }
    __syncthreads();

    float fv[64];
    #pragma unroll
    for (int c = 0; c < 64; c++) fv[c] = fu[c][ml];
    #pragma unroll 2
    for (int oo = 0; oo < 8; oo++) {
        int o = 8 * p + oo;
        float acc = 0.f;
        const float4* wp4 = (const float4*)(fl_w1 + o * 64);
        #pragma unroll
        for (int c4 = 0; c4 < 16; c4++) {
            float4 ww = __ldg(&wp4[c4]);
            acc += ww.x * fv[4 * c4] + ww.y * fv[4 * c4 + 1] +
                   ww.z * fv[4 * c4 + 2] + ww.w * fv[4 * c4 + 3];
        }
        o1s[o][ml] = fmaxf(fl_s1[o] * acc + fl_t1[o], 0.f);
    }
    __syncthreads();

    float ov[64];
    #pragma unroll
    for (int c = 0; c < 64; c++) ov[c] = o1s[c][ml];
    #pragma unroll 2
    for (int oo = 0; oo < 8; oo++) {
        int o = 8 * p + oo;
        float acc = fl_b2[o];
        const float4* wp4 = (const float4*)(fl_w2 + o * 64);
        #pragma unroll
        for (int c4 = 0; c4 < 16; c4++) {
            float4 ww = __ldg(&wp4[c4]);
            acc += ww.x * ov[4 * c4] + ww.y * ov[4 * c4 + 1] +
                   ww.z * ov[4 * c4 + 2] + ww.w * ov[4 * c4 + 3];
        }
        out[((size_t)b * 64 + o) * NM + m] = acc;
    }
}

extern "C" void kernel_launch(void* const* d_in, const int* in_sizes, int n_in,
                              void* d_out, int out_size)
{
    const float* x_label      = (const float*)d_in[0];
    const float* x_object     = (const float*)d_in[1];
    const float* template_xyz = (const float*)d_in[2];
    const float* mlp_w1 = (const float*)d_in[3];
    const float* mlp_s1 = (const float*)d_in[4];
    const float* mlp_t1 = (const float*)d_in[5];
    const float* mlp_w2 = (const float*)d_in[6];
    const float* mlp_s2 = (const float*)d_in[7];
    const float* mlp_t2 = (const float*)d_in[8];
    const float* gw_w1  = (const float*)d_in[9];
    const float* gw_b1  = (const float*)d_in[10];
    const float* gw_s   = (const float*)d_in[11];
    const float* gw_t   = (const float*)d_in[12];
    const float* gw_w2  = (const float*)d_in[13];
    const float* gw_b2  = (const float*)d_in[14];
    const float* gm_w1  = (const float*)d_in[15];
    const float* gm_s1  = (const float*)d_in[16];
    const float* gm_t1  = (const float*)d_in[17];
    const float* gm_w2  = (const float*)d_in[18];
    const float* gm_s2  = (const float*)d_in[19];
    const float* gm_t2  = (const float*)d_in[20];
    const float* fl_w1  = (const float*)d_in[21];
    const float* fl_s1  = (const float*)d_in[22];
    const float* fl_t1  = (const float*)d_in[23];
    const float* fl_w2  = (const float*)d_in[24];
    const float* fl_b2  = (const float*)d_in[25];

    k_gpool<<<512, 128>>>(x_label, x_object, template_xyz,
                          gw_w1, gw_b1, gw_s, gw_t, gw_w2, gw_b2,
                          gm_w1, gm_s1, gm_t1, gm_w2, gm_s2, gm_t2);
    k_out<<<512, 256>>>(x_label, x_object, template_xyz,
                        mlp_w1, mlp_s1, mlp_t1, mlp_w2, mlp_s2, mlp_t2,
                        fl_w1, fl_s1, fl_t1, fl_w2, fl_b2, (float*)d_out);
}